// round 4
// baseline (speedup 1.0000x reference)
#include <cuda_runtime.h>

// NablaT 3D: out[z,y,x] = bdiff_z(x0) + bdiff_y(x1) + bdiff_x(x2)
// bdiff along dim d: out[i] = a - b, a = (i>0)? v[i-1] : 0, b = (i<S-1)? v[i] : 0
//
// x: [3, 320, 320, 320] fp32. out: [320,320,320] fp32.
// One thread per float4 of output, flat 256-thread blocks (100% occupancy shape).
// Left-halo scalar obtained via warp shuffle from the neighbor's v2.w
// (only lane 0 loads it). Streaming store keeps output out of L2.

#define S 320
#define PLANE (S * S)           // 102400
#define VOL   (S * S * S)       // 32768000
#define X4    (S / 4)           // 80
#define P4    (PLANE / 4)       // 25600
#define NV4   (VOL / 4)         // 8192000 float4 outputs

__global__ __launch_bounds__(256)
void nablat_kernel(const float* __restrict__ xin, float* __restrict__ out) {
    const unsigned t = blockIdx.x * 256u + threadIdx.x;  // flat float4 index == [z,y,x4]

    const unsigned x4  = t % X4;
    const unsigned rem = t / X4;
    const unsigned y   = rem % S;
    const unsigned z   = rem / S;

    const float4* __restrict__ p0 = (const float4*)(xin);
    const float4* __restrict__ p1 = (const float4*)(xin + (long)VOL);
    const float4* __restrict__ p2 = (const float4*)(xin + 2L * VOL);
    const float*  __restrict__ s2 = xin + 2L * VOL;

    const float4 zero = make_float4(0.f, 0.f, 0.f, 0.f);

    // axis 0 (z): a0 = x0[z-1], b0 = x0[z] (b zeroed at z==S-1)
    float4 b0 = (z < S - 1) ? __ldg(&p0[t])      : zero;
    float4 a0 = (z > 0)     ? __ldg(&p0[t - P4]) : zero;

    // axis 1 (y): a1 = x1[y-1], b1 = x1[y]
    float4 b1 = (y < S - 1) ? __ldg(&p1[t])      : zero;
    float4 a1 = (y > 0)     ? __ldg(&p1[t - X4]) : zero;

    // axis 2 (x): row vector; left halo comes from lane-1's v2.w via shuffle.
    float4 v2 = __ldg(&p2[t]);

    const unsigned lane = threadIdx.x & 31u;
    float prev = __shfl_up_sync(0xffffffffu, v2.w, 1);
    if (lane == 0 && x4 > 0)  // warp-edge: fetch the one scalar we can't shuffle
        prev = __ldg(&s2[(long)t * 4 - 1]);
    if (x4 == 0)              // x == 0 boundary: a = 0 (overrides stale shuffle)
        prev = 0.f;

    float b2w = (x4 == X4 - 1) ? 0.f : v2.w;   // x == S-1 boundary

    float4 o;
    o.x = (a0.x - b0.x) + (a1.x - b1.x) + (prev - v2.x);
    o.y = (a0.y - b0.y) + (a1.y - b1.y) + (v2.x - v2.y);
    o.z = (a0.z - b0.z) + (a1.z - b1.z) + (v2.y - v2.z);
    o.w = (a0.w - b0.w) + (a1.w - b1.w) + (v2.z - b2w);

    __stcs(&((float4*)out)[t], o);   // streaming: output never re-read
}

extern "C" void kernel_launch(void* const* d_in, const int* in_sizes, int n_in,
                              void* d_out, int out_size) {
    const float* x = (const float*)d_in[0];
    float* out = (float*)d_out;

    nablat_kernel<<<NV4 / 256, 256>>>(x, out);   // 32000 blocks, exact fit
}

// round 5
// speedup vs baseline: 1.0038x; 1.0038x over previous
#include <cuda_runtime.h>

// NablaT 3D: out[z,y,x] = bdiff_z(x0) + bdiff_y(x1) + bdiff_x(x2)
// bdiff along dim d: out[i] = a - b, a = (i>0)? v[i-1] : 0, b = (i<S-1)? v[i] : 0
//
// x: [3, 320, 320, 320] fp32. out: [320,320,320] fp32.
// One thread per float4 of output. Flat 512-thread blocks (64 warps/SM shape).
// Left halo via warp shuffle (lane 0 loads the single scalar). Streaming store.
// All indexing in 32-bit (each array = 131 MB < 4 GB byte range).

#define S 320
#define PLANE (S * S)           // 102400
#define VOL   (S * S * S)       // 32768000
#define X4    (S / 4)           // 80
#define P4    (PLANE / 4)       // 25600
#define NV4   (VOL / 4)         // 8192000 float4 outputs

__global__ __launch_bounds__(512)
void nablat_kernel(const float* __restrict__ xin, float* __restrict__ out) {
    const unsigned t = blockIdx.x * 512u + threadIdx.x;  // flat float4 index == [z,y,x4]

    const unsigned x4  = t % X4;
    const unsigned rem = t / X4;
    const unsigned y   = rem % S;
    const unsigned z   = rem / S;

    const float4* __restrict__ p0 = (const float4*)(xin);
    const float4* __restrict__ p1 = p0 + (unsigned)(VOL / 4);
    const float4* __restrict__ p2 = p0 + 2u * (unsigned)(VOL / 4);
    const float*  __restrict__ s2 = (const float*)p2;

    const float4 zero = make_float4(0.f, 0.f, 0.f, 0.f);

    // axis 0 (z): a0 = x0[z-1], b0 = x0[z] (b zeroed at z==S-1)
    float4 a0 = (z > 0)     ? __ldg(&p0[t - P4]) : zero;
    float4 b0 = (z < S - 1) ? __ldg(&p0[t])      : zero;

    // axis 1 (y): a1 = x1[y-1], b1 = x1[y]
    float4 a1 = (y > 0)     ? __ldg(&p1[t - X4]) : zero;
    float4 b1 = (y < S - 1) ? __ldg(&p1[t])      : zero;

    // axis 2 (x): row vector; left halo from lane-1's v2.w via shuffle.
    float4 v2 = __ldg(&p2[t]);

    const unsigned lane = threadIdx.x & 31u;
    float prev = __shfl_up_sync(0xffffffffu, v2.w, 1);
    if (lane == 0 && x4 > 0)  // warp edge: fetch the one scalar we can't shuffle
        prev = __ldg(&s2[t * 4u - 1u]);
    if (x4 == 0)              // x == 0 boundary: a = 0
        prev = 0.f;

    float b2w = (x4 == X4 - 1) ? 0.f : v2.w;   // x == S-1 boundary

    float4 o;
    o.x = (a0.x - b0.x) + (a1.x - b1.x) + (prev - v2.x);
    o.y = (a0.y - b0.y) + (a1.y - b1.y) + (v2.x - v2.y);
    o.z = (a0.z - b0.z) + (a1.z - b1.z) + (v2.y - v2.z);
    o.w = (a0.w - b0.w) + (a1.w - b1.w) + (v2.z - b2w);

    __stcs(&((float4*)out)[t], o);   // streaming: output never re-read
}

extern "C" void kernel_launch(void* const* d_in, const int* in_sizes, int n_in,
                              void* d_out, int out_size) {
    const float* x = (const float*)d_in[0];
    float* out = (float*)d_out;

    nablat_kernel<<<NV4 / 512, 512>>>(x, out);   // 16000 blocks, exact fit
}